// round 1
// baseline (speedup 1.0000x reference)
#include <cuda_runtime.h>
#include <cuda_bf16.h>

// Problem constants
#define BB 4
#define SS 4096
#define DD 1024
#define MM (BB * SS)          // 16384
#define CH 64                 // scan chunks per sequence
#define LL (SS / CH)          // 64 elements per chunk

// ---------------------------------------------------------------------------
// Device scratch (allocation-free per harness rules)
// ---------------------------------------------------------------------------
__device__ float g_bufG[MM * DD];   // sigmoid(g)
__device__ float g_bufV[MM * DD];   // tanh(v)
__device__ float g_bufA[MM * DD];   // decay a
__device__ float g_cA[BB * CH * DD];
__device__ float g_cH[BB * CH * DD];
__device__ float g_hin[BB * CH * DD];

// ---------------------------------------------------------------------------
// Fused GEMM + activation.  y = x @ W^T + b, per blockIdx.z:
//   z=0 : sigmoid(y) -> g_bufG
//   z=1 : tanh(y)    -> g_bufV
//   z=2 : 0.001 + 0.998*sigmoid(y) -> g_bufA
// Classic 128x128x8 SGEMM, 256 threads, 8x8 per-thread tile.
// ---------------------------------------------------------------------------
__device__ __forceinline__ float fast_sigmoid(float x) {
    return 1.0f / (1.0f + __expf(-x));
}

__global__ __launch_bounds__(256)
void gemm3_act_kernel(const float* __restrict__ X,
                      const float* __restrict__ Wg, const float* __restrict__ bg,
                      const float* __restrict__ Wv, const float* __restrict__ bv,
                      const float* __restrict__ Wd, const float* __restrict__ bd)
{
    const int z = blockIdx.z;
    const float* __restrict__ W    = (z == 0) ? Wg : (z == 1) ? Wv : Wd;
    const float* __restrict__ bias = (z == 0) ? bg : (z == 1) ? bv : bd;
    float* __restrict__ out        = (z == 0) ? g_bufG : (z == 1) ? g_bufV : g_bufA;

    __shared__ float As[8][128];
    __shared__ float Bs[8][128];

    const int tid = threadIdx.x;
    const int bm = blockIdx.y * 128;
    const int bn = blockIdx.x * 128;

    // global->shared load mapping: each thread loads one float4 of A and B
    const int lrow = tid >> 1;            // 0..127
    const int lk   = (tid & 1) * 4;       // 0 or 4

    // compute mapping: 16x16 thread grid, 8x8 tile each
    const int tx = tid & 15;
    const int ty = tid >> 4;

    float acc[8][8];
    #pragma unroll
    for (int i = 0; i < 8; ++i)
        #pragma unroll
        for (int j = 0; j < 8; ++j)
            acc[i][j] = 0.0f;

    const float* aPtr = X + (size_t)(bm + lrow) * DD + lk;
    const float* bPtr = W + (size_t)(bn + lrow) * DD + lk;

    for (int k0 = 0; k0 < DD; k0 += 8) {
        float4 av = *reinterpret_cast<const float4*>(aPtr);
        float4 bv4 = *reinterpret_cast<const float4*>(bPtr);
        As[lk + 0][lrow] = av.x;
        As[lk + 1][lrow] = av.y;
        As[lk + 2][lrow] = av.z;
        As[lk + 3][lrow] = av.w;
        Bs[lk + 0][lrow] = bv4.x;
        Bs[lk + 1][lrow] = bv4.y;
        Bs[lk + 2][lrow] = bv4.z;
        Bs[lk + 3][lrow] = bv4.w;
        __syncthreads();

        #pragma unroll
        for (int k = 0; k < 8; ++k) {
            float a[8], b[8];
            // two float4 loads each (broadcast-friendly)
            float4 a0 = *reinterpret_cast<const float4*>(&As[k][ty * 8]);
            float4 a1 = *reinterpret_cast<const float4*>(&As[k][ty * 8 + 4]);
            float4 b0 = *reinterpret_cast<const float4*>(&Bs[k][tx * 8]);
            float4 b1 = *reinterpret_cast<const float4*>(&Bs[k][tx * 8 + 4]);
            a[0]=a0.x; a[1]=a0.y; a[2]=a0.z; a[3]=a0.w;
            a[4]=a1.x; a[5]=a1.y; a[6]=a1.z; a[7]=a1.w;
            b[0]=b0.x; b[1]=b0.y; b[2]=b0.z; b[3]=b0.w;
            b[4]=b1.x; b[5]=b1.y; b[6]=b1.z; b[7]=b1.w;
            #pragma unroll
            for (int i = 0; i < 8; ++i)
                #pragma unroll
                for (int j = 0; j < 8; ++j)
                    acc[i][j] = fmaf(a[i], b[j], acc[i][j]);
        }
        __syncthreads();

        aPtr += 8;
        bPtr += 8;
    }

    // epilogue: bias + activation
    #pragma unroll
    for (int i = 0; i < 8; ++i) {
        const int row = bm + ty * 8 + i;
        float* orow = out + (size_t)row * DD + bn + tx * 8;
        #pragma unroll
        for (int j = 0; j < 8; ++j) {
            const int col = bn + tx * 8 + j;
            float val = acc[i][j] + bias[col];
            float r;
            if (z == 0) {
                r = fast_sigmoid(val);
            } else if (z == 1) {
                r = tanhf(val);
            } else {
                r = 0.001f + 0.998f * fast_sigmoid(val);
            }
            orow[j] = r;
        }
    }
}

// ---------------------------------------------------------------------------
// Scan pass 1: per (b, chunk, d) compute chunk summary (A = prod a, H = chunk
// scan result with h0 = 0).
// grid: (DD/256, CH, BB), block 256
// ---------------------------------------------------------------------------
__global__ __launch_bounds__(256)
void scan_pass1_kernel()
{
    const int d = blockIdx.x * 256 + threadIdx.x;
    const int c = blockIdx.y;
    const int b = blockIdx.z;

    size_t base = ((size_t)(b * SS + c * LL)) * DD + d;
    float A = 1.0f;
    float h = 0.0f;
    #pragma unroll 4
    for (int s = 0; s < LL; ++s) {
        float a  = g_bufA[base];
        float xg = g_bufG[base];
        float xv = g_bufV[base];
        float xx = xg * xv;
        A *= a;
        h = fmaf(a, h, xx);
        base += DD;
    }
    const size_t ci = (size_t)(b * CH + c) * DD + d;
    g_cA[ci] = A;
    g_cH[ci] = h;
}

// ---------------------------------------------------------------------------
// Scan pass 2: per (b, d), sequential scan over CH chunk summaries to get
// the carry-in h for each chunk.
// grid: (DD/256, BB), block 256
// ---------------------------------------------------------------------------
__global__ __launch_bounds__(256)
void scan_pass2_kernel()
{
    const int d = blockIdx.x * 256 + threadIdx.x;
    const int b = blockIdx.y;

    float h = 0.0f;
    #pragma unroll 4
    for (int c = 0; c < CH; ++c) {
        const size_t ci = (size_t)(b * CH + c) * DD + d;
        g_hin[ci] = h;
        h = fmaf(g_cA[ci], h, g_cH[ci]);
    }
}

// ---------------------------------------------------------------------------
// Scan pass 3: per (b, chunk, d) re-run chunk scan with correct carry-in,
// write final output.
// grid: (DD/256, CH, BB), block 256
// ---------------------------------------------------------------------------
__global__ __launch_bounds__(256)
void scan_pass3_kernel(float* __restrict__ out)
{
    const int d = blockIdx.x * 256 + threadIdx.x;
    const int c = blockIdx.y;
    const int b = blockIdx.z;

    size_t base = ((size_t)(b * SS + c * LL)) * DD + d;
    float h = g_hin[(size_t)(b * CH + c) * DD + d];
    #pragma unroll 4
    for (int s = 0; s < LL; ++s) {
        float a  = g_bufA[base];
        float xg = g_bufG[base];
        float xv = g_bufV[base];
        h = fmaf(a, h, xg * xv);
        out[base] = h;
        base += DD;
    }
}

// ---------------------------------------------------------------------------
// Launch
// ---------------------------------------------------------------------------
extern "C" void kernel_launch(void* const* d_in, const int* in_sizes, int n_in,
                              void* d_out, int out_size)
{
    const float* x  = (const float*)d_in[0];
    const float* Wg = (const float*)d_in[1];
    const float* bg = (const float*)d_in[2];
    const float* Wv = (const float*)d_in[3];
    const float* bv = (const float*)d_in[4];
    const float* Wd = (const float*)d_in[5];
    const float* bd = (const float*)d_in[6];
    float* out = (float*)d_out;

    // GEMM + activations: grid (N/128, M/128, 3)
    dim3 gemmGrid(DD / 128, MM / 128, 3);
    gemm3_act_kernel<<<gemmGrid, 256>>>(x, Wg, bg, Wv, bv, Wd, bd);

    // Scan
    dim3 p1(DD / 256, CH, BB);
    scan_pass1_kernel<<<p1, 256>>>();

    dim3 p2(DD / 256, BB);
    scan_pass2_kernel<<<p2, 256>>>();

    scan_pass3_kernel<<<p1, 256>>>(out);
}

// round 3
// speedup vs baseline: 2.7140x; 2.7140x over previous
#include <cuda_runtime.h>
#include <cuda_bf16.h>
#include <cstdint>

// Problem constants
#define BB 4
#define SS 4096
#define DD 1024
#define MM (BB * SS)          // 16384
#define CH 64
#define LL (SS / CH)          // 64

// GEMM config: Y[M, 3072] = Ae[M, 3072k] @ Be[3072n, 3072k]^T  (K' = 3*DD)
#define KTOT (3 * DD)         // 3072
#define NTOT (3 * DD)         // 3072 output cols (g | v | d)
#define CTA_M 128
#define CTA_N 256
#define KC2 64                // k per stage
#define NC (KTOT / KC2)       // 48 stages

#define SWZ(o) ((uint32_t)(o) ^ ((((uint32_t)(o)) >> 3) & 0x70))

#define STAGE_BYTES 49152     // A: 128*128B = 16KB, B: 256*128B = 32KB
#define OFF_B 16384
#define SMEM_GEMM (2 * STAGE_BYTES)

// ---------------------------------------------------------------------------
// Device scratch
// ---------------------------------------------------------------------------
__device__ __nv_bfloat16 g_Ae[(size_t)MM * KTOT];     // [xh | xh | xl]
__device__ __nv_bfloat16 g_Be[(size_t)NTOT * KTOT];   // per row: [wh | wl | wh]
__device__ float g_bufG[(size_t)MM * DD];
__device__ float g_bufV[(size_t)MM * DD];
__device__ float g_bufA[(size_t)MM * DD];
__device__ float g_cA[BB * CH * DD];
__device__ float g_cH[BB * CH * DD];
__device__ float g_hin[BB * CH * DD];

// ---------------------------------------------------------------------------
// PTX helpers
// ---------------------------------------------------------------------------
__device__ __forceinline__ uint32_t smem_u32(const void* p) {
    uint32_t a;
    asm("{ .reg .u64 t; cvta.to.shared.u64 t, %1; cvt.u32.u64 %0, t; }" : "=r"(a) : "l"(p));
    return a;
}

#define CP_ASYNC16(sm, gp) \
    asm volatile("cp.async.cg.shared.global [%0], [%1], 16;" :: "r"(sm), "l"(gp))
#define CP_COMMIT() asm volatile("cp.async.commit_group;" ::: "memory")
#define CP_WAIT(N)  asm volatile("cp.async.wait_group %0;" :: "n"(N) : "memory")

#define LDSM_X4(r0, r1, r2, r3, addr) \
    asm volatile("ldmatrix.sync.aligned.m8n8.x4.shared.b16 {%0,%1,%2,%3}, [%4];" \
                 : "=r"(r0), "=r"(r1), "=r"(r2), "=r"(r3) : "r"(addr))

#define MMA_BF16(c, a, b) \
    asm volatile("mma.sync.aligned.m16n8k16.row.col.f32.bf16.bf16.f32 " \
                 "{%0,%1,%2,%3}, {%4,%5,%6,%7}, {%8,%9}, {%0,%1,%2,%3};" \
                 : "+f"((c)[0]), "+f"((c)[1]), "+f"((c)[2]), "+f"((c)[3]) \
                 : "r"((a)[0]), "r"((a)[1]), "r"((a)[2]), "r"((a)[3]), \
                   "r"((b)[0]), "r"((b)[1]))

// ---------------------------------------------------------------------------
// Split kernels: fp32 -> bf16 hi/lo into concatenated-K layouts
// ---------------------------------------------------------------------------
__global__ __launch_bounds__(256)
void splitX_kernel(const float* __restrict__ x)
{
    int i = blockIdx.x * 256 + threadIdx.x;            // float4 index
    if (i >= MM * DD / 4) return;
    float4 v = reinterpret_cast<const float4*>(x)[i];
    int lin = i * 4;
    int m = lin >> 10;           // /DD
    int k = lin & 1023;
    float f[4] = {v.x, v.y, v.z, v.w};
    unsigned short h[4], l[4];
#pragma unroll
    for (int q = 0; q < 4; ++q) {
        __nv_bfloat16 hb = __float2bfloat16(f[q]);
        __nv_bfloat16 lb = __float2bfloat16(f[q] - __bfloat162float(hb));
        h[q] = __bfloat16_as_ushort(hb);
        l[q] = __bfloat16_as_ushort(lb);
    }
    ushort4 hv = make_ushort4(h[0], h[1], h[2], h[3]);
    ushort4 lv = make_ushort4(l[0], l[1], l[2], l[3]);
    size_t base = (size_t)m * KTOT + k;
    *reinterpret_cast<ushort4*>(g_Ae + base)            = hv;   // xh
    *reinterpret_cast<ushort4*>(g_Ae + base + DD)       = hv;   // xh
    *reinterpret_cast<ushort4*>(g_Ae + base + 2 * DD)   = lv;   // xl
}

__global__ __launch_bounds__(256)
void splitW_kernel(const float* __restrict__ w, int z)
{
    int i = blockIdx.x * 256 + threadIdx.x;
    if (i >= DD * DD / 4) return;
    float4 v = reinterpret_cast<const float4*>(w)[i];
    int lin = i * 4;
    int n = lin >> 10;
    int k = lin & 1023;
    float f[4] = {v.x, v.y, v.z, v.w};
    unsigned short h[4], l[4];
#pragma unroll
    for (int q = 0; q < 4; ++q) {
        __nv_bfloat16 hb = __float2bfloat16(f[q]);
        __nv_bfloat16 lb = __float2bfloat16(f[q] - __bfloat162float(hb));
        h[q] = __bfloat16_as_ushort(hb);
        l[q] = __bfloat16_as_ushort(lb);
    }
    ushort4 hv = make_ushort4(h[0], h[1], h[2], h[3]);
    ushort4 lv = make_ushort4(l[0], l[1], l[2], l[3]);
    size_t base = (size_t)(z * DD + n) * KTOT + k;
    *reinterpret_cast<ushort4*>(g_Be + base)          = hv;   // wh
    *reinterpret_cast<ushort4*>(g_Be + base + DD)     = lv;   // wl
    *reinterpret_cast<ushort4*>(g_Be + base + 2 * DD) = hv;   // wh
}

// ---------------------------------------------------------------------------
// bf16 HMMA GEMM + activation epilogue
// grid (NTOT/CTA_N = 12, MM/CTA_M = 128), 512 threads, 16 warps of 32x64
// ---------------------------------------------------------------------------
__global__ __launch_bounds__(512, 1)
void gemm_hmma_kernel(const float* __restrict__ bg,
                      const float* __restrict__ bv,
                      const float* __restrict__ bd)
{
    extern __shared__ char smem[];
    const uint32_t smb = smem_u32(smem);

    const int tid  = threadIdx.x;
    const int wid  = tid >> 5;
    const int lane = tid & 31;
    const int wm = wid & 3;          // m-tile of 32
    const int wn = wid >> 2;         // n-tile of 64

    const int bn = blockIdx.x * CTA_N;
    const int bm = blockIdx.y * CTA_M;

    const __nv_bfloat16* Ab = g_Ae + (size_t)bm * KTOT;
    const __nv_bfloat16* Bb = g_Be + (size_t)bn * KTOT;

    float acc[2][8][4];
#pragma unroll
    for (int i = 0; i < 2; ++i)
#pragma unroll
        for (int j = 0; j < 8; ++j)
#pragma unroll
            for (int q = 0; q < 4; ++q) acc[i][j][q] = 0.0f;

    // prefetch helper (stage s, k-chunk c)
    auto prefetch = [&](int c, int s) {
        const uint32_t stA = smb + s * STAGE_BYTES;
        const uint32_t stB = stA + OFF_B;
        const size_t kb = (size_t)c * KC2;
        // A: 1024 16B chunks
#pragma unroll
        for (int it = 0; it < 2; ++it) {
            int u = tid + it * 512;
            int row = u >> 3, cc = u & 7;
            const char* gp = reinterpret_cast<const char*>(Ab + (size_t)row * KTOT + kb) + cc * 16;
            CP_ASYNC16(stA + SWZ(row * 128 + cc * 16), gp);
        }
        // B: 2048 16B chunks
#pragma unroll
        for (int it = 0; it < 4; ++it) {
            int u = tid + it * 512;
            int row = u >> 3, cc = u & 7;
            const char* gp = reinterpret_cast<const char*>(Bb + (size_t)row * KTOT + kb) + cc * 16;
            CP_ASYNC16(stB + SWZ(row * 128 + cc * 16), gp);
        }
    };

    prefetch(0, 0);
    CP_COMMIT();

    for (int c = 0; c < NC; ++c) {
        const int s = c & 1;
        __syncthreads();                   // all warps done with buffer we're about to fill
        if (c + 1 < NC) {
            prefetch(c + 1, s ^ 1);
            CP_COMMIT();
            CP_WAIT(1);
        } else {
            CP_WAIT(0);
        }
        __syncthreads();                   // stage s visible to all

        const uint32_t stA = smb + s * STAGE_BYTES;
        const uint32_t stB = stA + OFF_B;

#pragma unroll
        for (int ks = 0; ks < KC2 / 16; ++ks) {
            uint32_t af[2][4];
#pragma unroll
            for (int mi = 0; mi < 2; ++mi) {
                int rowA = wm * 32 + mi * 16 + (lane & 15);
                uint32_t addr = stA + SWZ(rowA * 128 + ks * 32 + (lane >> 4) * 16);
                LDSM_X4(af[mi][0], af[mi][1], af[mi][2], af[mi][3], addr);
            }
            uint32_t bf[8][2];
#pragma unroll
            for (int p = 0; p < 4; ++p) {
                int nrow = wn * 64 + p * 16 + (lane & 7) + ((lane >> 4) << 3);
                uint32_t addr = stB + SWZ(nrow * 128 + ks * 32 + ((lane >> 3) & 1) * 16);
                uint32_t r0, r1, r2, r3;
                LDSM_X4(r0, r1, r2, r3, addr);
                bf[2 * p][0] = r0; bf[2 * p][1] = r1;
                bf[2 * p + 1][0] = r2; bf[2 * p + 1][1] = r3;
            }
#pragma unroll
            for (int mi = 0; mi < 2; ++mi)
#pragma unroll
                for (int ni = 0; ni < 8; ++ni)
                    MMA_BF16(acc[mi][ni], af[mi], bf[ni]);
        }
    }

    // Epilogue: bias + activation, write fp32
    const int z = bn >> 10;                 // 0,1,2
    const int nloc = bn & 1023;
    const float* bias = (z == 0) ? bg : (z == 1) ? bv : bd;
    float* outp = (z == 0) ? g_bufG : (z == 1) ? g_bufV : g_bufA;

#pragma unroll
    for (int mi = 0; mi < 2; ++mi) {
#pragma unroll
        for (int ni = 0; ni < 8; ++ni) {
            int row0 = bm + wm * 32 + mi * 16 + (lane >> 2);
            int col  = nloc + wn * 64 + ni * 8 + (lane & 3) * 2;
            float b0 = bias[col], b1 = bias[col + 1];
#pragma unroll
            for (int half = 0; half < 2; ++half) {
                int row = row0 + half * 8;
                float v0 = acc[mi][ni][half * 2 + 0] + b0;
                float v1 = acc[mi][ni][half * 2 + 1] + b1;
                float r0, r1;
                if (z == 0) {
                    r0 = 1.0f / (1.0f + __expf(-v0));
                    r1 = 1.0f / (1.0f + __expf(-v1));
                } else if (z == 1) {
                    r0 = tanhf(v0);
                    r1 = tanhf(v1);
                } else {
                    r0 = 0.001f + 0.998f / (1.0f + __expf(-v0));
                    r1 = 0.001f + 0.998f / (1.0f + __expf(-v1));
                }
                float2 o2; o2.x = r0; o2.y = r1;
                *reinterpret_cast<float2*>(outp + (size_t)row * DD + col) = o2;
            }
        }
    }
}

// ---------------------------------------------------------------------------
// Scan passes
// ---------------------------------------------------------------------------
__global__ __launch_bounds__(256)
void scan_pass1_kernel()
{
    const int d = blockIdx.x * 256 + threadIdx.x;
    const int c = blockIdx.y;
    const int b = blockIdx.z;

    size_t base = ((size_t)(b * SS + c * LL)) * DD + d;
    float A = 1.0f;
    float h = 0.0f;
#pragma unroll 4
    for (int s = 0; s < LL; ++s) {
        float a  = g_bufA[base];
        float xg = g_bufG[base];
        float xv = g_bufV[base];
        A *= a;
        h = fmaf(a, h, xg * xv);
        base += DD;
    }
    const size_t ci = (size_t)(b * CH + c) * DD + d;
    g_cA[ci] = A;
    g_cH[ci] = h;
}

__global__ __launch_bounds__(256)
void scan_pass2_kernel()
{
    const int d = blockIdx.x * 256 + threadIdx.x;
    const int b = blockIdx.y;

    float h = 0.0f;
#pragma unroll 4
    for (int c = 0; c < CH; ++c) {
        const size_t ci = (size_t)(b * CH + c) * DD + d;
        g_hin[ci] = h;
        h = fmaf(g_cA[ci], h, g_cH[ci]);
    }
}

__global__ __launch_bounds__(256)
void scan_pass3_kernel(float* __restrict__ out)
{
    const int d = blockIdx.x * 256 + threadIdx.x;
    const int c = blockIdx.y;
    const int b = blockIdx.z;

    size_t base = ((size_t)(b * SS + c * LL)) * DD + d;
    float h = g_hin[(size_t)(b * CH + c) * DD + d];
#pragma unroll 4
    for (int s = 0; s < LL; ++s) {
        float a  = g_bufA[base];
        float xg = g_bufG[base];
        float xv = g_bufV[base];
        h = fmaf(a, h, xg * xv);
        out[base] = h;
        base += DD;
    }
}

// ---------------------------------------------------------------------------
// Launch
// ---------------------------------------------------------------------------
extern "C" void kernel_launch(void* const* d_in, const int* in_sizes, int n_in,
                              void* d_out, int out_size)
{
    const float* x  = (const float*)d_in[0];
    const float* Wg = (const float*)d_in[1];
    const float* bg = (const float*)d_in[2];
    const float* Wv = (const float*)d_in[3];
    const float* bv = (const float*)d_in[4];
    const float* Wd = (const float*)d_in[5];
    const float* bd = (const float*)d_in[6];
    float* out = (float*)d_out;

    static int smem_set = 0;
    if (!smem_set) {
        cudaFuncSetAttribute(gemm_hmma_kernel,
                             cudaFuncAttributeMaxDynamicSharedMemorySize, SMEM_GEMM);
        smem_set = 1;
    }

    splitX_kernel<<<(MM * DD / 4 + 255) / 256, 256>>>(x);
    splitW_kernel<<<(DD * DD / 4 + 255) / 256, 256>>>(Wg, 0);
    splitW_kernel<<<(DD * DD / 4 + 255) / 256, 256>>>(Wv, 1);
    splitW_kernel<<<(DD * DD / 4 + 255) / 256, 256>>>(Wd, 2);

    gemm_hmma_kernel<<<dim3(NTOT / CTA_N, MM / CTA_M), 512, SMEM_GEMM>>>(bg, bv, bd);

    dim3 p1(DD / 256, CH, BB);
    scan_pass1_kernel<<<p1, 256>>>();
    dim3 p2(DD / 256, BB);
    scan_pass2_kernel<<<p2, 256>>>();
    scan_pass3_kernel<<<p1, 256>>>(out);
}